// round 7
// baseline (speedup 1.0000x reference)
#include <cuda_runtime.h>
#include <cstdint>

#define SEQ 256
#define BATCH 64
#define EMBD 512
#define HID 1024
#define GATE 4096
#define VOCAB 128
#define NCTA 128
#define NTHR 256
#define BH (BATCH*HID)

// smem layout (float indices)
#define AF_F  0                    // recurrence A-fragments: 8192 uint4 = 32768 floats
#define BS0_F 32768                // recurrence B stage buf0: 64 x 132
#define BS1_F (32768+8448)         // buf1
#define GS_F  (32768+16896)        // gate scratch: [2][32][68] = 4352 floats
#define SMEM_FLOATS (32768+16896+4352)   // 54016 floats = 216064 B
// phases reuse: AS at 0 (128x132=16896), BS at 16896 (64x132=8448)

__device__ float g_XW[(size_t)SEQ*BATCH*GATE];
__device__ float g_ys0[(size_t)SEQ*BH];
__device__ float g_h1[2*BH];
__device__ unsigned g_barGen, g_barCnt;

__device__ __forceinline__ uint32_t tf(float f){
    uint32_t r; asm("cvt.rna.tf32.f32 %0, %1;":"=r"(r):"f"(f)); return r;
}
__device__ __forceinline__ uint4 tf4(float4 v){
    uint4 o; o.x=tf(v.x); o.y=tf(v.y); o.z=tf(v.z); o.w=tf(v.w); return o;
}
__device__ __forceinline__ void mma8(float &d0,float &d1,float &d2,float &d3,
                                     uint4 a, uint32_t b0, uint32_t b1){
    asm volatile("mma.sync.aligned.m16n8k8.row.col.f32.tf32.tf32.f32 "
                 "{%0,%1,%2,%3},{%4,%5,%6,%7},{%8,%9},{%0,%1,%2,%3};"
                 :"+f"(d0),"+f"(d1),"+f"(d2),"+f"(d3)
                 :"r"(a.x),"r"(a.y),"r"(a.z),"r"(a.w),"r"(b0),"r"(b1));
}

__device__ __forceinline__ void gridbar(unsigned &gen){
    __syncthreads();
    if(threadIdx.x==0){
        const unsigned target=gen+1u;
        __threadfence();
        unsigned a=atomicAdd(&g_barCnt,1u);
        if(a==(unsigned)(gridDim.x-1)){ g_barCnt=0u; __threadfence(); atomicExch(&g_barGen,target); }
        else { while((int)(*((volatile unsigned*)&g_barGen)-target)<0){} }
        __threadfence();
    }
    gen++; __syncthreads();
}

// ---- phase GEMM: C[token][gate] = A(token,:) . W(gate,:) + bias ----------
// tile M=128 tokens x N=64 gates; 8 warps: wm(4) x wn(2); K chunks of 128.
__device__ void phase_gemm(const int *xidx,const float *emb,const float *Adir,
                           int Kdim,const float *W,const float *bias,float *C,
                           float *sm){
    const int tid=threadIdx.x, lane=tid&31, wid=tid>>5;
    const int wm=wid&3, wn=wid>>2;
    uint32_t *AS=(uint32_t*)sm;          // [128][132] tf32 bits
    uint32_t *BS=(uint32_t*)(sm+16896);  // [64][132]
    const int g=lane>>2, tg=lane&3;

    for(int tile=blockIdx.x; tile<128*64; tile+=NCTA){
        const int mt=tile>>6, ntg=tile&63;
        const int m0=mt*128, n0=ntg*64;
        float d[2][4][4];
#pragma unroll
        for(int a=0;a<2;a++)
#pragma unroll
        for(int b=0;b<4;b++)
#pragma unroll
        for(int c=0;c<4;c++) d[a][b][c]=0.f;

        for(int kc=0; kc<Kdim/128; kc++){
            __syncthreads();
#pragma unroll
            for(int i=0;i<16;i++){
                int idx=tid+i*NTHR, r=idx>>5, q=idx&31;
                const float *src = xidx
                    ? emb+(size_t)xidx[m0+r]*EMBD + kc*128 + 4*q
                    : Adir+(size_t)(m0+r)*Kdim + kc*128 + 4*q;
                *(uint4*)&AS[r*132+4*q]=tf4(*(const float4*)src);
            }
#pragma unroll
            for(int i=0;i<8;i++){
                int idx=tid+i*NTHR, r=idx>>5, q=idx&31;
                float4 v=*(const float4*)&W[(size_t)(n0+r)*Kdim + kc*128 + 4*q];
                *(uint4*)&BS[r*132+4*q]=tf4(v);
            }
            __syncthreads();
#pragma unroll 4
            for(int ks=0; ks<16; ks++){
                const int kk=ks*8+tg;
                uint4 af[2]; uint32_t b0[4],b1[4];
#pragma unroll
                for(int mi=0;mi<2;mi++){
                    int m=wm*32+mi*16+g;
                    af[mi].x=AS[m*132+kk];     af[mi].y=AS[(m+8)*132+kk];
                    af[mi].z=AS[m*132+kk+4];   af[mi].w=AS[(m+8)*132+kk+4];
                }
#pragma unroll
                for(int nt=0;nt<4;nt++){
                    int n=wn*32+nt*8+g;
                    b0[nt]=BS[n*132+kk]; b1[nt]=BS[n*132+kk+4];
                }
#pragma unroll
                for(int mi=0;mi<2;mi++)
#pragma unroll
                for(int nt=0;nt<4;nt++)
                    mma8(d[mi][nt][0],d[mi][nt][1],d[mi][nt][2],d[mi][nt][3],
                         af[mi],b0[nt],b1[nt]);
            }
        }
#pragma unroll
        for(int mi=0;mi<2;mi++){
            int m=m0+wm*32+mi*16+g;
#pragma unroll
            for(int nt=0;nt<4;nt++){
                int n=n0+wn*32+nt*8+2*tg;
                float2 v0={d[mi][nt][0]+bias[n], d[mi][nt][1]+bias[n+1]};
                float2 v1={d[mi][nt][2]+bias[n], d[mi][nt][3]+bias[n+1]};
                *(float2*)&C[(size_t)m*GATE+n]=v0;
                *(float2*)&C[(size_t)(m+8)*GATE+n]=v1;
            }
        }
    }
}

// ---- LSTM recurrence: CTA owns 8 hidden units (32 gate rows), N=64 batch --
// 8 warps: wn(2 x 32 batch) x wm(2 x 16 rows) x wk(2 x K=512 split).
__device__ void lstm_layer(const float *xw_all,const float *h0L,const float *c0L,
                           const float *Whh,int layer,float *outH,float *outC,
                           float *sm,unsigned &gen){
    const int tid=threadIdx.x, lane=tid&31, wid=tid>>5;
    const int wn=wid&1, wm=(wid>>1)&1, wk=wid>>2;
    const int u0=blockIdx.x*8;
    const int g=lane>>2, tg=lane&3;
    uint4 *AF=(uint4*)(sm+AF_F);               // [128 ks][2 wm][32 lane]
    uint32_t *BSbuf[2]={(uint32_t*)(sm+BS0_F),(uint32_t*)(sm+BS1_F)}; // [64][132]
    float *GS=sm+GS_F;                         // [2][32][68]

    // pre-gather Whh slice into fragment-linear tf32 layout (once per layer)
    for(int idx=tid; idx<8192; idx+=NTHR){
        int ks=idx>>6, mt=(idx>>5)&1, l=idx&31;
        int m=mt*16+(l>>2), k=ks*8+(l&3);
        int r0=((m  )>>3)*HID+u0+((m  )&7);
        int r1=((m+8)>>3)*HID+u0+((m+8)&7);
        uint4 v;
        v.x=tf(Whh[(size_t)r0*HID+k]);
        v.y=tf(Whh[(size_t)r1*HID+k]);
        v.z=tf(Whh[(size_t)r0*HID+k+4]);
        v.w=tf(Whh[(size_t)r1*HID+k+4]);
        AF[(ks*2+mt)*32+l]=v;
    }
    float cst[2];
#pragma unroll
    for(int i=0;i<2;i++){
        int p=tid+i*NTHR, u=p>>6, b=p&63;
        cst[i]=c0L[b*HID+u0+u];
    }
    __syncthreads();

    for(int t=0;t<SEQ;t++){
        const float *hsrc=(t==0)?h0L:(layer==0? g_ys0+(size_t)(t-1)*BH
                                              : g_h1+(size_t)((t-1)&1)*BH);
        float d[4][4];
#pragma unroll
        for(int a=0;a<4;a++)
#pragma unroll
        for(int b=0;b<4;b++) d[a][b]=0.f;

        // stage mapping: idx=tid+i*NTHR -> r=idx>>5, q=idx&31 (8 float4/thread)
        float4 rg[8];
#pragma unroll
        for(int i=0;i<8;i++){
            int idx=tid+i*NTHR, r=idx>>5, q=idx&31;
            rg[i]=*(const float4*)&hsrc[(size_t)r*HID + 4*q];
        }
#pragma unroll
        for(int i=0;i<8;i++){
            int idx=tid+i*NTHR, r=idx>>5, q=idx&31;
            *(uint4*)&BSbuf[0][r*132+4*q]=tf4(rg[i]);
        }
        __syncthreads();

        for(int c=0;c<8;c++){
            if(c<7){
#pragma unroll
                for(int i=0;i<8;i++){
                    int idx=tid+i*NTHR, r=idx>>5, q=idx&31;
                    rg[i]=*(const float4*)&hsrc[(size_t)r*HID + (c+1)*128 + 4*q];
                }
            }
            const uint32_t *BS=BSbuf[c&1];
#pragma unroll 4
            for(int ks2=0; ks2<8; ks2++){
                const int ks=c*16+wk*8+ks2;     // global k-step (AF index)
                const int kcol=wk*64+ks2*8+tg;  // column within this 128-chunk
                uint4 af=AF[(ks*2+wm)*32+lane];
                uint32_t b0[4],b1[4];
#pragma unroll
                for(int nt=0;nt<4;nt++){
                    int n=wn*32+nt*8+g;
                    b0[nt]=BS[n*132+kcol];
                    b1[nt]=BS[n*132+kcol+4];
                }
#pragma unroll
                for(int nt=0;nt<4;nt++)
                    mma8(d[nt][0],d[nt][1],d[nt][2],d[nt][3],af,b0[nt],b1[nt]);
            }
            if(c<7){
#pragma unroll
                for(int i=0;i<8;i++){
                    int idx=tid+i*NTHR, r=idx>>5, q=idx&31;
                    *(uint4*)&BSbuf[(c+1)&1][r*132+4*q]=tf4(rg[i]);
                }
            }
            __syncthreads();
        }
        // D -> gate scratch (per k-half), then reduce in pointwise
#pragma unroll
        for(int nt=0;nt<4;nt++){
            int m=wm*16+g, n=wn*32+nt*8+2*tg;
            float *gs=GS+wk*2176;
            gs[m*68+n]=d[nt][0];     gs[m*68+n+1]=d[nt][1];
            gs[(m+8)*68+n]=d[nt][2]; gs[(m+8)*68+n+1]=d[nt][3];
        }
        __syncthreads();
        const float *xwt=xw_all+(size_t)t*BATCH*GATE;
        float *dst=(layer==0)? g_ys0+(size_t)t*BH : g_h1+(size_t)(t&1)*BH;
#pragma unroll
        for(int i=0;i<2;i++){
            int p=tid+i*NTHR, u=p>>6, b=p&63;
            const float *xwb=xwt+(size_t)b*GATE+u0+u;
            float ig=GS[(0*8+u)*68+b]+GS[2176+(0*8+u)*68+b]+xwb[0*HID];
            float fg=GS[(1*8+u)*68+b]+GS[2176+(1*8+u)*68+b]+xwb[1*HID];
            float gg=GS[(2*8+u)*68+b]+GS[2176+(2*8+u)*68+b]+xwb[2*HID];
            float og=GS[(3*8+u)*68+b]+GS[2176+(3*8+u)*68+b]+xwb[3*HID];
            ig=1.f/(1.f+__expf(-ig));
            fg=1.f/(1.f+__expf(-fg));
            og=1.f/(1.f+__expf(-og));
            gg=tanhf(gg);
            float cc=fg*cst[i]+ig*gg;
            cst[i]=cc;
            float h=og*tanhf(cc);
            dst[b*HID+u0+u]=h;
            if(t==SEQ-1){ outH[b*HID+u0+u]=h; outC[b*HID+u0+u]=cc; }
        }
        gridbar(gen);
    }
}

__device__ void fc_phase(const float *hlast,const float *Wfc,const float *bfc,float *out){
    const int v=blockIdx.x, tid=threadIdx.x;
    if(tid<BATCH){
        float s=0.f;
#pragma unroll 4
        for(int k=0;k<HID;k+=4){
            float4 hh=*(const float4*)&hlast[tid*HID+k];
            float4 ww=*(const float4*)&Wfc[(size_t)v*HID+k];
            s+=hh.x*ww.x+hh.y*ww.y+hh.z*ww.z+hh.w*ww.w;
        }
        out[tid*VOCAB+v]=s+bfc[v];
    }
}

__global__ void __launch_bounds__(NTHR,1) lstm_all_kernel(
    const int *x,const float *h0,const float *c0,const float *embt,
    const float *Wih0,const float *Whh0,const float *b0,
    const float *Wih1,const float *Whh1,const float *b1,
    const float *Wfc,const float *bfc,float *out){
    extern __shared__ float sm[];
    unsigned gen=*((volatile unsigned*)&g_barGen);

    phase_gemm(x,embt,nullptr,EMBD,Wih0,b0,g_XW,sm);
    gridbar(gen);
    lstm_layer(g_XW,h0,c0,Whh0,0,
               out+VOCAB*BATCH, out+VOCAB*BATCH+2*BH, sm,gen);
    gridbar(gen);
    phase_gemm(nullptr,nullptr,g_ys0,HID,Wih1,b1,g_XW,sm);
    gridbar(gen);
    lstm_layer(g_XW,h0+BH,c0+BH,Whh1,1,
               out+VOCAB*BATCH+BH, out+VOCAB*BATCH+3*BH, sm,gen);
    fc_phase(g_h1+BH,Wfc,bfc,out);
}

extern "C" void kernel_launch(void *const *d_in,const int *in_sizes,int n_in,
                              void *d_out,int out_size){
    const int   *x   =(const int*)d_in[0];
    const float *h0  =(const float*)d_in[1];
    const float *c0  =(const float*)d_in[2];
    const float *embt=(const float*)d_in[3];
    const float *Wih0=(const float*)d_in[4];
    const float *Whh0=(const float*)d_in[5];
    const float *b0  =(const float*)d_in[6];
    const float *Wih1=(const float*)d_in[7];
    const float *Whh1=(const float*)d_in[8];
    const float *b1  =(const float*)d_in[9];
    const float *Wfc =(const float*)d_in[10];
    const float *bfc =(const float*)d_in[11];
    float *out=(float*)d_out;
    const int smemBytes=SMEM_FLOATS*(int)sizeof(float);   // 216064 B
    cudaFuncSetAttribute(lstm_all_kernel,
                         cudaFuncAttributeMaxDynamicSharedMemorySize,smemBytes);
    lstm_all_kernel<<<NCTA,NTHR,smemBytes>>>(x,h0,c0,embt,Wih0,Whh0,b0,
                                             Wih1,Whh1,b1,Wfc,bfc,out);
}

// round 10
// speedup vs baseline: 1.1462x; 1.1462x over previous
#include <cuda_runtime.h>
#include <cstdint>

#define SEQ 256
#define BATCH 64
#define EMBD 512
#define HID 1024
#define GATE 4096
#define VOCAB 128
#define NCTA 128
#define NTHR 256
#define BH (BATCH*HID)

// smem layout (float indices)
#define AF_F  0                      // A-fragments: 8192 uint4 = 32768 floats (128KB)
#define BS0_F 32768                  // B stage buf0: 128 x 72
#define BS1_F (32768+9216)           // buf1
#define GS_F  (32768+18432)          // gate scratch: [2][32][68] = 4352 floats
#define SMEM_FLOATS (32768+18432+4352)   // 55552 floats = 222208 B
// phases reuse: AS at 0 (128x132), BS at 16896 (64x132)

__device__ float g_XW[(size_t)SEQ*BATCH*GATE];   // transposed: [s][gate n][b]
__device__ float g_ys0[(size_t)SEQ*BH];          // [s][b][k] (phase-B input)
__device__ float g_hT[2][HID*BATCH];             // transposed h ping-pong [k][b]
__device__ unsigned g_barGen, g_barCnt;

__device__ __forceinline__ uint32_t tf(float f){
    uint32_t r; asm("cvt.rna.tf32.f32 %0, %1;":"=r"(r):"f"(f)); return r;
}
__device__ __forceinline__ uint4 tf4(float4 v){
    uint4 o; o.x=tf(v.x); o.y=tf(v.y); o.z=tf(v.z); o.w=tf(v.w); return o;
}
__device__ __forceinline__ void mma8(float &d0,float &d1,float &d2,float &d3,
                                     uint4 a, uint32_t b0, uint32_t b1){
    asm volatile("mma.sync.aligned.m16n8k8.row.col.f32.tf32.tf32.f32 "
                 "{%0,%1,%2,%3},{%4,%5,%6,%7},{%8,%9},{%0,%1,%2,%3};"
                 :"+f"(d0),"+f"(d1),"+f"(d2),"+f"(d3)
                 :"r"(a.x),"r"(a.y),"r"(a.z),"r"(a.w),"r"(b0),"r"(b1));
}

__device__ __forceinline__ void gridbar(unsigned &gen){
    __syncthreads();
    if(threadIdx.x==0){
        const unsigned target=gen+1u;
        __threadfence();
        unsigned a=atomicAdd(&g_barCnt,1u);
        if(a==(unsigned)(gridDim.x-1)){ g_barCnt=0u; __threadfence(); atomicExch(&g_barGen,target); }
        else { while((int)(*((volatile unsigned*)&g_barGen)-target)<0){} }
        __threadfence();
    }
    gen++; __syncthreads();
}

// ---- phase GEMM: XWT[s][n][b] = A(token,:) . W(n,:) + bias[n] ------------
// tile M=128 tokens x N=64 gates; 8 warps: wm(4) x wn(2); K chunks of 128.
__device__ void phase_gemm(const int *xidx,const float *emb,const float *Adir,
                           int Kdim,const float *W,const float *bias,float *C,
                           float *sm){
    const int tid=threadIdx.x, lane=tid&31, wid=tid>>5;
    const int wm=wid&3, wn=wid>>2;
    uint32_t *AS=(uint32_t*)sm;          // [128][132]
    uint32_t *BS=(uint32_t*)(sm+16896);  // [64][132]
    const int g=lane>>2, tg=lane&3;

    for(int tile=blockIdx.x; tile<128*64; tile+=NCTA){
        const int mt=tile>>6, ntg=tile&63;
        const int m0=mt*128, n0=ntg*64;
        float d[2][4][4];
#pragma unroll
        for(int a=0;a<2;a++)
#pragma unroll
        for(int b=0;b<4;b++)
#pragma unroll
        for(int c=0;c<4;c++) d[a][b][c]=0.f;

        for(int kc=0; kc<Kdim/128; kc++){
            __syncthreads();
#pragma unroll
            for(int i=0;i<16;i++){
                int idx=tid+i*NTHR, r=idx>>5, q=idx&31;
                const float *src = xidx
                    ? emb+(size_t)xidx[m0+r]*EMBD + kc*128 + 4*q
                    : Adir+(size_t)(m0+r)*Kdim + kc*128 + 4*q;
                *(uint4*)&AS[r*132+4*q]=tf4(*(const float4*)src);
            }
#pragma unroll
            for(int i=0;i<8;i++){
                int idx=tid+i*NTHR, r=idx>>5, q=idx&31;
                float4 v=*(const float4*)&W[(size_t)(n0+r)*Kdim + kc*128 + 4*q];
                *(uint4*)&BS[r*132+4*q]=tf4(v);
            }
            __syncthreads();
#pragma unroll 4
            for(int ks=0; ks<16; ks++){
                const int kk=ks*8+tg;
                uint4 af[2]; uint32_t b0[4],b1[4];
#pragma unroll
                for(int mi=0;mi<2;mi++){
                    int m=wm*32+mi*16+g;
                    af[mi].x=AS[m*132+kk];     af[mi].y=AS[(m+8)*132+kk];
                    af[mi].z=AS[m*132+kk+4];   af[mi].w=AS[(m+8)*132+kk+4];
                }
#pragma unroll
                for(int nt=0;nt<4;nt++){
                    int n=wn*32+nt*8+g;
                    b0[nt]=BS[n*132+kk]; b1[nt]=BS[n*132+kk+4];
                }
#pragma unroll
                for(int mi=0;mi<2;mi++)
#pragma unroll
                for(int nt=0;nt<4;nt++)
                    mma8(d[mi][nt][0],d[mi][nt][1],d[mi][nt][2],d[mi][nt][3],
                         af[mi],b0[nt],b1[nt]);
            }
        }
        // epilogue -> transposed C[s][n][b]
#pragma unroll
        for(int mi=0;mi<2;mi++){
            int m=m0+wm*32+mi*16+g;
            int s1=m>>6,  bt1=m&63;
            int s2=(m+8)>>6, bt2=(m+8)&63;
#pragma unroll
            for(int nt=0;nt<4;nt++){
                int n=n0+wn*32+nt*8+2*tg;
                size_t ba=((size_t)s1*GATE+n)*64+bt1;
                C[ba]   =d[mi][nt][0]+bias[n];
                C[ba+64]=d[mi][nt][1]+bias[n+1];
                size_t bb=((size_t)s2*GATE+n)*64+bt2;
                C[bb]   =d[mi][nt][2]+bias[n];
                C[bb+64]=d[mi][nt][3]+bias[n+1];
            }
        }
    }
}

// ---- LSTM recurrence: CTA owns 8 hidden units (32 gate rows), N=64 batch --
// 8 warps: wn(2) x wm(2) x wk(2, K split). Per-step gridbar (proven safe).
__device__ void lstm_layer(const float *xwT,const float *h0L,const float *c0L,
                           const float *Whh,int layer,float *outH,float *outC,
                           float *sm,unsigned &gen){
    const int tid=threadIdx.x, lane=tid&31, wid=tid>>5;
    const int wn=wid&1, wm=(wid>>1)&1, wk=wid>>2;
    const int u0=blockIdx.x*8;
    const int g=lane>>2, tg=lane&3;
    uint4 *AF=(uint4*)(sm+AF_F);               // [128 ks][2 wm][32 lane]
    uint32_t *BSb[2]={(uint32_t*)(sm+BS0_F),(uint32_t*)(sm+BS1_F)}; // [128][72]
    float *GS=sm+GS_F;                         // [2][32][68]

    // pre-gather Whh slice into fragment-linear tf32 layout (once per layer)
    for(int idx=tid; idx<8192; idx+=NTHR){
        int ks=idx>>6, mt=(idx>>5)&1, l=idx&31;
        int m=mt*16+(l>>2), k=ks*8+(l&3);
        int r0=((m  )>>3)*HID+u0+((m  )&7);
        int r1=((m+8)>>3)*HID+u0+((m+8)&7);
        uint4 v;
        v.x=tf(Whh[(size_t)r0*HID+k]);
        v.y=tf(Whh[(size_t)r1*HID+k]);
        v.z=tf(Whh[(size_t)r0*HID+k+4]);
        v.w=tf(Whh[(size_t)r1*HID+k+4]);
        AF[(ks*2+mt)*32+l]=v;
    }
    float cst[2];
#pragma unroll
    for(int i=0;i<2;i++){
        int p=tid+i*NTHR, u=p>>6, b=p&63;
        cst[i]=c0L[b*HID+u0+u];
    }
    __syncthreads();

    for(int t=0;t<SEQ;t++){
        // prefetch this step's XW (independent of h): coalesced from XWT
        float xwreg[2][4];
#pragma unroll
        for(int i=0;i<2;i++){
            int p=tid+i*NTHR, u=p>>6, b=p&63;
            size_t base=((size_t)t*GATE + u0+u)*64 + b;
#pragma unroll
            for(int gt=0;gt<4;gt++) xwreg[i][gt]=xwT[base + (size_t)gt*HID*64];
        }

        const uint4 *hTsrc=(const uint4*)g_hT[t&1];
        float d[4][4];
#pragma unroll
        for(int a=0;a<4;a++)
#pragma unroll
        for(int b=0;b<4;b++) d[a][b]=0.f;

        // stage chunk 0
        uint4 rg[8];
        if(t>0){
#pragma unroll
            for(int i=0;i<8;i++) rg[i]=hTsrc[tid+i*NTHR];
        }else{
#pragma unroll
            for(int i=0;i<8;i++){
                int idx=tid+i*NTHR, kl=idx>>4, b4=4*(idx&15);
                float4 v;
                v.x=h0L[(b4+0)*HID + kl];
                v.y=h0L[(b4+1)*HID + kl];
                v.z=h0L[(b4+2)*HID + kl];
                v.w=h0L[(b4+3)*HID + kl];
                rg[i]=tf4(v);
            }
        }
#pragma unroll
        for(int i=0;i<8;i++){
            int idx=tid+i*NTHR;
            *(uint4*)&BSb[0][(idx>>4)*72 + 4*(idx&15)]=rg[i];
        }
        __syncthreads();

        for(int c=0;c<8;c++){
            if(c<7){
                if(t>0){
#pragma unroll
                    for(int i=0;i<8;i++) rg[i]=hTsrc[(c+1)*2048 + tid+i*NTHR];
                }else{
#pragma unroll
                    for(int i=0;i<8;i++){
                        int idx=tid+i*NTHR, kl=idx>>4, b4=4*(idx&15);
                        float4 v;
                        v.x=h0L[(b4+0)*HID + (c+1)*128 + kl];
                        v.y=h0L[(b4+1)*HID + (c+1)*128 + kl];
                        v.z=h0L[(b4+2)*HID + (c+1)*128 + kl];
                        v.w=h0L[(b4+3)*HID + (c+1)*128 + kl];
                        rg[i]=tf4(v);
                    }
                }
            }
            const uint32_t *BS=BSb[c&1];
#pragma unroll 4
            for(int ks2=0; ks2<8; ks2++){
                const int ks=c*16+wk*8+ks2;
                const int kcol=wk*64+ks2*8+tg;
                uint4 af=AF[(ks*2+wm)*32+lane];
                uint32_t b0[4],b1[4];
#pragma unroll
                for(int nt=0;nt<4;nt++){
                    int n=wn*32+nt*8+g;
                    b0[nt]=BS[kcol*72+n];
                    b1[nt]=BS[(kcol+4)*72+n];
                }
#pragma unroll
                for(int nt=0;nt<4;nt++)
                    mma8(d[nt][0],d[nt][1],d[nt][2],d[nt][3],af,b0[nt],b1[nt]);
            }
            if(c<7){
#pragma unroll
                for(int i=0;i<8;i++){
                    int idx=tid+i*NTHR;
                    *(uint4*)&BSb[(c+1)&1][(idx>>4)*72 + 4*(idx&15)]=rg[i];
                }
            }
            __syncthreads();
        }
        // D -> gate scratch (per k-half)
#pragma unroll
        for(int nt=0;nt<4;nt++){
            int m=wm*16+g, n=wn*32+nt*8+2*tg;
            float *gs=GS+wk*2176;
            gs[m*68+n]=d[nt][0];     gs[m*68+n+1]=d[nt][1];
            gs[(m+8)*68+n]=d[nt][2]; gs[(m+8)*68+n+1]=d[nt][3];
        }
        __syncthreads();
        // pointwise
        float *hTd=g_hT[(t+1)&1];
#pragma unroll
        for(int i=0;i<2;i++){
            int p=tid+i*NTHR, u=p>>6, b=p&63;
            float ig=GS[(0*8+u)*68+b]+GS[2176+(0*8+u)*68+b]+xwreg[i][0];
            float fg=GS[(1*8+u)*68+b]+GS[2176+(1*8+u)*68+b]+xwreg[i][1];
            float gg=GS[(2*8+u)*68+b]+GS[2176+(2*8+u)*68+b]+xwreg[i][2];
            float og=GS[(3*8+u)*68+b]+GS[2176+(3*8+u)*68+b]+xwreg[i][3];
            ig=1.f/(1.f+__expf(-ig));
            fg=1.f/(1.f+__expf(-fg));
            og=1.f/(1.f+__expf(-og));
            gg=tanhf(gg);
            float cc=fg*cst[i]+ig*gg;
            cst[i]=cc;
            float h=og*tanhf(cc);
            float hr=__uint_as_float(tf(h));       // tf32-rounded (what MMAs consume)
            hTd[(u0+u)*64 + b]=hr;                 // coalesced
            if(layer==0) g_ys0[(size_t)t*BH + b*HID + u0+u]=hr;
            if(t==SEQ-1){ outH[b*HID+u0+u]=h; outC[b*HID+u0+u]=cc; }
        }
        gridbar(gen);   // proven-safe step barrier
    }
}

__device__ void fc_phase(const float *hlast,const float *Wfc,const float *bfc,float *out){
    const int v=blockIdx.x, tid=threadIdx.x;
    if(tid<BATCH){
        float s=0.f;
#pragma unroll 4
        for(int k=0;k<HID;k+=4){
            float4 hh=*(const float4*)&hlast[tid*HID+k];
            float4 ww=*(const float4*)&Wfc[(size_t)v*HID+k];
            s+=hh.x*ww.x+hh.y*ww.y+hh.z*ww.z+hh.w*ww.w;
        }
        out[tid*VOCAB+v]=s+bfc[v];
    }
}

__global__ void __launch_bounds__(NTHR,1) lstm_all_kernel(
    const int *x,const float *h0,const float *c0,const float *embt,
    const float *Wih0,const float *Whh0,const float *b0,
    const float *Wih1,const float *Whh1,const float *b1,
    const float *Wfc,const float *bfc,float *out){
    extern __shared__ float sm[];
    unsigned gen=*((volatile unsigned*)&g_barGen);

    phase_gemm(x,embt,nullptr,EMBD,Wih0,b0,g_XW,sm);
    gridbar(gen);
    lstm_layer(g_XW,h0,c0,Whh0,0,
               out+VOCAB*BATCH, out+VOCAB*BATCH+2*BH, sm,gen);
    phase_gemm(nullptr,nullptr,g_ys0,HID,Wih1,b1,g_XW,sm);
    gridbar(gen);
    lstm_layer(g_XW,h0+BH,c0+BH,Whh1,1,
               out+VOCAB*BATCH+BH, out+VOCAB*BATCH+3*BH, sm,gen);
    fc_phase(out+VOCAB*BATCH+BH,Wfc,bfc,out);
}

extern "C" void kernel_launch(void *const *d_in,const int *in_sizes,int n_in,
                              void *d_out,int out_size){
    const int   *x   =(const int*)d_in[0];
    const float *h0  =(const float*)d_in[1];
    const float *c0  =(const float*)d_in[2];
    const float *embt=(const float*)d_in[3];
    const float *Wih0=(const float*)d_in[4];
    const float *Whh0=(const float*)d_in[5];
    const float *b0  =(const float*)d_in[6];
    const float *Wih1=(const float*)d_in[7];
    const float *Whh1=(const float*)d_in[8];
    const float *b1  =(const float*)d_in[9];
    const float *Wfc =(const float*)d_in[10];
    const float *bfc =(const float*)d_in[11];
    float *out=(float*)d_out;
    const int smemBytes=SMEM_FLOATS*(int)sizeof(float);   // 222208 B
    cudaFuncSetAttribute(lstm_all_kernel,
                         cudaFuncAttributeMaxDynamicSharedMemorySize,smemBytes);
    lstm_all_kernel<<<NCTA,NTHR,smemBytes>>>(x,h0,c0,embt,Wih0,Whh0,b0,
                                             Wih1,Whh1,b1,Wfc,bfc,out);
}

// round 12
// speedup vs baseline: 1.6657x; 1.4532x over previous
#include <cuda_runtime.h>
#include <cstdint>

#define SEQ 256
#define BATCH 64
#define EMBD 512
#define HID 1024
#define GATE 4096
#define VOCAB 128
#define NCTA 128
#define NTHR 256
#define BH (BATCH*HID)

// smem float offsets
#define A0_F 0          // L0 A stage: 2 x 1024 uint4 = 8192 floats
#define A1_F 8192       // L1 A stage: 2 x 1024 uint4 = 8192 floats
#define BS_F 16384      // B stage: 2 x [128][72] = 18432 floats
#define GS_F 34816      // gate scratch: [2 wk][32][72] = 4608 floats
#define BIAS_F 39424    // b1 slice: 32 floats
#define SMEM_FLOATS 39456
// phase_gemm reuses [0, 25344)

__device__ float g_XW[(size_t)SEQ*BATCH*GATE];   // [s][n][b] layer-0 input gates (256MB)
__device__ float g_in1T[2][2048*BATCH];          // ping-pong [k][b]; rows 0-1023 ys0/h0, 1024-2047 h1
__device__ float g_W0f[(size_t)128*8*4096];      // Whh0 fragment-linear tf32 (16MB)
__device__ float g_W1f[(size_t)128*16*4096];     // [Wih1|Whh1] fragment-linear tf32 (32MB)
__device__ unsigned g_barGen, g_barCnt;

__device__ __forceinline__ uint32_t tf(float f){
    uint32_t r; asm("cvt.rna.tf32.f32 %0, %1;":"=r"(r):"f"(f)); return r;
}
__device__ __forceinline__ uint4 tf4(float4 v){
    uint4 o; o.x=tf(v.x); o.y=tf(v.y); o.z=tf(v.z); o.w=tf(v.w); return o;
}
__device__ __forceinline__ void mma8(float &d0,float &d1,float &d2,float &d3,
                                     uint4 a, uint32_t b0, uint32_t b1){
    asm volatile("mma.sync.aligned.m16n8k8.row.col.f32.tf32.tf32.f32 "
                 "{%0,%1,%2,%3},{%4,%5,%6,%7},{%8,%9},{%0,%1,%2,%3};"
                 :"+f"(d0),"+f"(d1),"+f"(d2),"+f"(d3)
                 :"r"(a.x),"r"(a.y),"r"(a.z),"r"(a.w),"r"(b0),"r"(b1));
}

__device__ __forceinline__ void gridbar(unsigned &gen){
    __syncthreads();
    if(threadIdx.x==0){
        const unsigned target=gen+1u;
        __threadfence();
        unsigned a=atomicAdd(&g_barCnt,1u);
        if(a==(unsigned)(gridDim.x-1)){ g_barCnt=0u; __threadfence(); atomicExch(&g_barGen,target); }
        else { while((int)(*((volatile unsigned*)&g_barGen)-target)<0){} }
        __threadfence();
    }
    gen++; __syncthreads();
}

// ---- one-time weight pre-gather into fragment-linear tf32 images ----------
// local row l (0..31) of CTA r -> global gate row (l>>3)*HID + r*8 + (l&7)
__device__ void fill_weights(const float* Whh0,const float* Wih1,const float* Whh1){
    int gtid=blockIdx.x*NTHR+threadIdx.x;
    for(int idx=gtid; idx<1048576; idx+=NCTA*NTHR){     // W0f [r][c 8][ks 16][wm 2][lane 32]
        int lane=idx&31, wm=(idx>>5)&1, ks=(idx>>6)&15, c=(idx>>10)&7, r=idx>>13;
        int l0=wm*16+(lane>>2), l1=l0+8;
        int k=c*128+ks*8+(lane&3);
        int ga=(l0>>3)*HID + r*8 + (l0&7);
        int gb=(l1>>3)*HID + r*8 + (l1&7);
        uint4 v;
        v.x=tf(Whh0[(size_t)ga*HID+k]);
        v.y=tf(Whh0[(size_t)gb*HID+k]);
        v.z=tf(Whh0[(size_t)ga*HID+k+4]);
        v.w=tf(Whh0[(size_t)gb*HID+k+4]);
        ((uint4*)g_W0f)[idx]=v;
    }
    for(int idx=gtid; idx<2097152; idx+=NCTA*NTHR){     // W1f [r][c 16][ks 16][wm 2][lane 32]
        int lane=idx&31, wm=(idx>>5)&1, ks=(idx>>6)&15, c=(idx>>10)&15, r=idx>>14;
        int l0=wm*16+(lane>>2), l1=l0+8;
        int k=c*128+ks*8+(lane&3);
        int ga=(l0>>3)*HID + r*8 + (l0&7);
        int gb=(l1>>3)*HID + r*8 + (l1&7);
        const float* S=(k<HID)? Wih1 : Whh1;
        int kk=(k<HID)? k : k-HID;
        uint4 v;
        v.x=tf(S[(size_t)ga*HID+kk]);
        v.y=tf(S[(size_t)gb*HID+kk]);
        v.z=tf(S[(size_t)ga*HID+kk+4]);
        v.w=tf(S[(size_t)gb*HID+kk+4]);
        ((uint4*)g_W1f)[idx]=v;
    }
}
__device__ void prefill(const float* h0){
    int gtid=blockIdx.x*NTHR+threadIdx.x;
    for(int idx=gtid; idx<HID*BATCH; idx+=NCTA*NTHR){
        int k=idx>>6, b=idx&63;
        g_in1T[0][idx]=__uint_as_float(tf(h0[(size_t)b*HID+k]));
        g_in1T[1][(size_t)HID*BATCH+idx]=__uint_as_float(tf(h0[(size_t)BH+(size_t)b*HID+k]));
    }
}

// ---- phase A GEMM (verbatim R10-proven): XW0[s][n][b]=emb[x]@Wih0^T+b0 ----
__device__ void phase_gemm(const int *xidx,const float *emb,int Kdim,
                           const float *W,const float *bias,float *C,float *sm){
    const int tid=threadIdx.x, lane=tid&31, wid=tid>>5;
    const int wm=wid&3, wn=wid>>2;
    uint32_t *AS=(uint32_t*)sm;          // [128][132]
    uint32_t *BS=(uint32_t*)(sm+16896);  // [64][132]
    const int g=lane>>2, tg=lane&3;
    for(int tile=blockIdx.x; tile<128*64; tile+=NCTA){
        const int mt=tile>>6, ntg=tile&63;
        const int m0=mt*128, n0=ntg*64;
        float d[2][4][4];
#pragma unroll
        for(int a=0;a<2;a++)
#pragma unroll
        for(int b=0;b<4;b++)
#pragma unroll
        for(int c=0;c<4;c++) d[a][b][c]=0.f;
        for(int kc=0; kc<Kdim/128; kc++){
            __syncthreads();
#pragma unroll
            for(int i=0;i<16;i++){
                int idx=tid+i*NTHR, rr=idx>>5, q=idx&31;
                const float *src=emb+(size_t)xidx[m0+rr]*EMBD + kc*128 + 4*q;
                *(uint4*)&AS[rr*132+4*q]=tf4(*(const float4*)src);
            }
#pragma unroll
            for(int i=0;i<8;i++){
                int idx=tid+i*NTHR, rr=idx>>5, q=idx&31;
                float4 v=*(const float4*)&W[(size_t)(n0+rr)*Kdim + kc*128 + 4*q];
                *(uint4*)&BS[rr*132+4*q]=tf4(v);
            }
            __syncthreads();
#pragma unroll 4
            for(int ks=0; ks<16; ks++){
                const int kk=ks*8+tg;
                uint4 af[2]; uint32_t b0[4],b1[4];
#pragma unroll
                for(int mi=0;mi<2;mi++){
                    int m=wm*32+mi*16+g;
                    af[mi].x=AS[m*132+kk];   af[mi].y=AS[(m+8)*132+kk];
                    af[mi].z=AS[m*132+kk+4]; af[mi].w=AS[(m+8)*132+kk+4];
                }
#pragma unroll
                for(int nt=0;nt<4;nt++){
                    int n=wn*32+nt*8+g;
                    b0[nt]=BS[n*132+kk]; b1[nt]=BS[n*132+kk+4];
                }
#pragma unroll
                for(int mi=0;mi<2;mi++)
#pragma unroll
                for(int nt=0;nt<4;nt++)
                    mma8(d[mi][nt][0],d[mi][nt][1],d[mi][nt][2],d[mi][nt][3],
                         af[mi],b0[nt],b1[nt]);
            }
        }
#pragma unroll
        for(int mi=0;mi<2;mi++){
            int m=m0+wm*32+mi*16+g;
            int s1=m>>6, bt1=m&63, s2=(m+8)>>6, bt2=(m+8)&63;
#pragma unroll
            for(int nt=0;nt<4;nt++){
                int n=n0+wn*32+nt*8+2*tg;
                size_t ba=((size_t)s1*GATE+n)*64+bt1;
                C[ba]   =d[mi][nt][0]+bias[n];
                C[ba+64]=d[mi][nt][1]+bias[n+1];
                size_t bb=((size_t)s2*GATE+n)*64+bt2;
                C[bb]   =d[mi][nt][2]+bias[n];
                C[bb+64]=d[mi][nt][3]+bias[n+1];
            }
        }
    }
}

// ---- one wavefront: CTA r does L0 step w (if w<SEQ) and L1 step w-1 (if w>=1)
__device__ void wave_step(int w,float* cst0,float* cst1,
                          float* outH0,float* outC0,float* outH1,float* outC1,
                          float* sm){
    const int tid=threadIdx.x, lane=tid&31, wid=tid>>5;
    const int wn=wid&1, wm=(wid>>1)&1, wk=wid>>2;
    const int g=lane>>2, tg=lane&3;
    const int r=blockIdx.x;
    const bool doL0=(w<SEQ), doL1=(w>=1);
    const float* bufR=g_in1T[w&1];
    float* bufW=g_in1T[(w+1)&1];
    const uint4* A0g=(const uint4*)g_W0f + (size_t)r*8192;
    const uint4* A1g=(const uint4*)g_W1f + (size_t)r*16384;
    uint4* A0s=(uint4*)(sm+A0_F);
    uint4* A1s=(uint4*)(sm+A1_F);
    uint32_t* BSs=(uint32_t*)(sm+BS_F);
    float* GS=sm+GS_F;

    // prefetch this step's XW gates (independent of h)
    float xw[2][4];
    if(doL0){
#pragma unroll
        for(int i=0;i<2;i++){
            int p=tid+i*NTHR, u=p>>6, b=p&63;
            size_t base=((size_t)w*GATE + r*8+u)*64 + b;
#pragma unroll
            for(int gt=0;gt<4;gt++) xw[i][gt]=g_XW[base+(size_t)gt*(HID*64)];
        }
    }
    // stage chunk 0 (regs -> STS), R10 pattern
    uint4 rB[8], rA0[4], rA1[4];
#pragma unroll
    for(int i=0;i<8;i++) rB[i]=*(const uint4*)&bufR[(size_t)(tid+i*NTHR)*4];
    if(doL0){
#pragma unroll
        for(int i=0;i<4;i++) rA0[i]=A0g[tid+i*NTHR];
    }
    if(doL1){
#pragma unroll
        for(int i=0;i<4;i++) rA1[i]=A1g[tid+i*NTHR];
    }
#pragma unroll
    for(int i=0;i<8;i++){
        int idx=tid+i*NTHR, k=idx>>4, q=idx&15;
        *(uint4*)&BSs[k*72+4*q]=rB[i];
    }
    if(doL0){
#pragma unroll
        for(int i=0;i<4;i++) A0s[tid+i*NTHR]=rA0[i];
    }
    if(doL1){
#pragma unroll
        for(int i=0;i<4;i++) A1s[tid+i*NTHR]=rA1[i];
    }
    __syncthreads();

    float d0[4][4], d1[4][4];
#pragma unroll
    for(int a=0;a<4;a++)
#pragma unroll
    for(int b=0;b<4;b++){ d0[a][b]=0.f; d1[a][b]=0.f; }

    for(int c=0;c<16;c++){
        if(c<15){
#pragma unroll
            for(int i=0;i<8;i++)
                rB[i]=*(const uint4*)&bufR[((size_t)(c+1)*2048 + tid+i*NTHR)*4];
            if(doL0 && c+1<8){
#pragma unroll
                for(int i=0;i<4;i++) rA0[i]=A0g[(c+1)*1024 + tid+i*NTHR];
            }
            if(doL1){
#pragma unroll
                for(int i=0;i<4;i++) rA1[i]=A1g[(c+1)*1024 + tid+i*NTHR];
            }
        }
        const uint4* A0=A0s+(c&1)*1024;
        const uint4* A1=A1s+(c&1)*1024;
        const uint32_t* BS=BSs+(c&1)*9216;
#pragma unroll 2
        for(int ks2=0;ks2<8;ks2++){
            const int ksl=wk*8+ks2, kcol=ksl*8+tg;
            uint32_t b0[4],b1[4];
#pragma unroll
            for(int nt=0;nt<4;nt++){
                int n=wn*32+nt*8+g;
                b0[nt]=BS[kcol*72+n]; b1[nt]=BS[(kcol+4)*72+n];
            }
            if(doL0 && c<8){
                uint4 a0=A0[(ksl*2+wm)*32+lane];
#pragma unroll
                for(int nt=0;nt<4;nt++)
                    mma8(d0[nt][0],d0[nt][1],d0[nt][2],d0[nt][3],a0,b0[nt],b1[nt]);
            }
            if(doL1){
                uint4 a1=A1[(ksl*2+wm)*32+lane];
#pragma unroll
                for(int nt=0;nt<4;nt++)
                    mma8(d1[nt][0],d1[nt][1],d1[nt][2],d1[nt][3],a1,b0[nt],b1[nt]);
            }
        }
        if(c<15){
#pragma unroll
            for(int i=0;i<8;i++){
                int idx=tid+i*NTHR, k=idx>>4, q=idx&15;
                *(uint4*)&BSs[((c+1)&1)*9216 + k*72+4*q]=rB[i];
            }
            if(doL0 && c+1<8){
#pragma unroll
                for(int i=0;i<4;i++) A0s[((c+1)&1)*1024 + tid+i*NTHR]=rA0[i];
            }
            if(doL1){
#pragma unroll
                for(int i=0;i<4;i++) A1s[((c+1)&1)*1024 + tid+i*NTHR]=rA1[i];
            }
        }
        __syncthreads();
    }
    // L0 epilogue + pointwise
    if(doL0){
#pragma unroll
        for(int nt=0;nt<4;nt++){
            int m=wm*16+g, n=wn*32+nt*8+2*tg;
            GS[wk*2304+m*72+n]      =d0[nt][0];
            GS[wk*2304+m*72+n+1]    =d0[nt][1];
            GS[wk*2304+(m+8)*72+n]  =d0[nt][2];
            GS[wk*2304+(m+8)*72+n+1]=d0[nt][3];
        }
    }
    __syncthreads();
    if(doL0){
#pragma unroll
        for(int i=0;i<2;i++){
            int p=tid+i*NTHR, u=p>>6, b=p&63;
            float ig=GS[(0*8+u)*72+b]+GS[2304+(0*8+u)*72+b]+xw[i][0];
            float fg=GS[(1*8+u)*72+b]+GS[2304+(1*8+u)*72+b]+xw[i][1];
            float gg=GS[(2*8+u)*72+b]+GS[2304+(2*8+u)*72+b]+xw[i][2];
            float og=GS[(3*8+u)*72+b]+GS[2304+(3*8+u)*72+b]+xw[i][3];
            ig=1.f/(1.f+__expf(-ig)); fg=1.f/(1.f+__expf(-fg));
            og=1.f/(1.f+__expf(-og)); gg=tanhf(gg);
            float cc=fg*cst0[i]+ig*gg; cst0[i]=cc;
            float h=og*tanhf(cc);
            bufW[(r*8+u)*64+b]=__uint_as_float(tf(h));
            if(w==SEQ-1){ outH0[b*HID+r*8+u]=h; outC0[b*HID+r*8+u]=cc; }
        }
    }
    __syncthreads();
    // L1 epilogue + pointwise
    if(doL1){
#pragma unroll
        for(int nt=0;nt<4;nt++){
            int m=wm*16+g, n=wn*32+nt*8+2*tg;
            GS[wk*2304+m*72+n]      =d1[nt][0];
            GS[wk*2304+m*72+n+1]    =d1[nt][1];
            GS[wk*2304+(m+8)*72+n]  =d1[nt][2];
            GS[wk*2304+(m+8)*72+n+1]=d1[nt][3];
        }
    }
    __syncthreads();
    if(doL1){
#pragma unroll
        for(int i=0;i<2;i++){
            int p=tid+i*NTHR, u=p>>6, b=p&63;
            float ig=GS[(0*8+u)*72+b]+GS[2304+(0*8+u)*72+b]+sm[BIAS_F+0*8+u];
            float fg=GS[(1*8+u)*72+b]+GS[2304+(1*8+u)*72+b]+sm[BIAS_F+1*8+u];
            float gg=GS[(2*8+u)*72+b]+GS[2304+(2*8+u)*72+b]+sm[BIAS_F+2*8+u];
            float og=GS[(3*8+u)*72+b]+GS[2304+(3*8+u)*72+b]+sm[BIAS_F+3*8+u];
            ig=1.f/(1.f+__expf(-ig)); fg=1.f/(1.f+__expf(-fg));
            og=1.f/(1.f+__expf(-og)); gg=tanhf(gg);
            float cc=fg*cst1[i]+ig*gg; cst1[i]=cc;
            float h=og*tanhf(cc);
            bufW[(size_t)(1024+r*8+u)*64+b]=__uint_as_float(tf(h));
            if(w-1==SEQ-1){ outH1[b*HID+r*8+u]=h; outC1[b*HID+r*8+u]=cc; }
        }
    }
}

__global__ void __launch_bounds__(NTHR,1) lstm_all_kernel(
    const int *x,const float *h0,const float *c0,const float *embt,
    const float *Wih0,const float *Whh0,const float *b0,
    const float *Wih1,const float *Whh1,const float *b1,
    const float *Wfc,const float *bfc,float *out){
    extern __shared__ float sm[];
    unsigned gen=*((volatile unsigned*)&g_barGen);
    const int r=blockIdx.x, tid=threadIdx.x;

    if(tid<32) sm[BIAS_F+tid]=b1[(tid>>3)*HID + r*8 + (tid&7)];
    fill_weights(Whh0,Wih1,Whh1);
    prefill(h0);
    phase_gemm(x,embt,EMBD,Wih0,b0,g_XW,sm);
    gridbar(gen);

    float cst0[2],cst1[2];
#pragma unroll
    for(int i=0;i<2;i++){
        int p=tid+i*NTHR, u=p>>6, b=p&63;
        cst0[i]=c0[(size_t)b*HID + r*8+u];
        cst1[i]=c0[(size_t)BH + (size_t)b*HID + r*8+u];
    }
    float* outH0=out+VOCAB*BATCH;
    float* outH1=out+VOCAB*BATCH+BH;
    float* outC0=out+VOCAB*BATCH+2*BH;
    float* outC1=out+VOCAB*BATCH+3*BH;

    for(int w=0;w<=SEQ;w++){
        wave_step(w,cst0,cst1,outH0,outC0,outH1,outC1,sm);
        gridbar(gen);
    }
    // FC: logits[b][v] = h1_last . Wfc[v] + bfc[v]  (one v per CTA)
    if(tid<BATCH){
        float s=0.f;
#pragma unroll 4
        for(int k=0;k<HID;k+=4){
            float4 hh=*(const float4*)&outH1[tid*HID+k];
            float4 ww=*(const float4*)&Wfc[(size_t)r*HID+k];
            s+=hh.x*ww.x+hh.y*ww.y+hh.z*ww.z+hh.w*ww.w;
        }
        out[tid*VOCAB+r]=s+bfc[r];
    }
}

extern "C" void kernel_launch(void *const *d_in,const int *in_sizes,int n_in,
                              void *d_out,int out_size){
    const int   *x   =(const int*)d_in[0];
    const float *h0  =(const float*)d_in[1];
    const float *c0  =(const float*)d_in[2];
    const float *embt=(const float*)d_in[3];
    const float *Wih0=(const float*)d_in[4];
    const float *Whh0=(const float*)d_in[5];
    const float *b0  =(const float*)d_in[6];
    const float *Wih1=(const float*)d_in[7];
    const float *Whh1=(const float*)d_in[8];
    const float *b1  =(const float*)d_in[9];
    const float *Wfc =(const float*)d_in[10];
    const float *bfc =(const float*)d_in[11];
    float *out=(float*)d_out;
    const int smemBytes=SMEM_FLOATS*(int)sizeof(float);   // 157,824 B
    cudaFuncSetAttribute(lstm_all_kernel,
                         cudaFuncAttributeMaxDynamicSharedMemorySize,smemBytes);
    lstm_all_kernel<<<NCTA,NTHR,smemBytes>>>(x,h0,c0,embt,Wih0,Whh0,b0,
                                             Wih1,Whh1,b1,Wfc,bfc,out);
}

// round 13
// speedup vs baseline: 1.7494x; 1.0503x over previous
#include <cuda_runtime.h>
#include <cstdint>

#define SEQ 256
#define BATCH 64
#define EMBD 512
#define HID 1024
#define GATE 4096
#define VOCAB 128
#define NCTA 128
#define NTHR 256
#define BH (BATCH*HID)

// smem float offsets
#define A0_F 0          // L0 A stage: 2 x 1024 uint4 = 8192 floats
#define A1_F 8192       // L1 A stage: 2 x 1024 uint4 = 8192 floats
#define BS_F 16384      // B stage: 2 x [128][72] = 18432 floats; GS overlays buf0 post-loop
#define GS_F BS_F       // gate scratch: [4 wk][32][72] = 9216 floats (after chunk loop)
#define BIAS_F 34816    // b1 slice: 32 floats
#define SMEM_FLOATS 34848
// phase_gemm reuses [0, 25344)

__device__ float g_XW[(size_t)SEQ*BATCH*GATE];   // [s][n][b] layer-0 input gates
__device__ float g_in1T[2][2048*BATCH];          // ping-pong [k][b]; rows 0-1023 ys0/h0, 1024-2047 h1
__device__ float g_W0f[(size_t)128*8*4096];      // Whh0 fragment-linear tf32 (16MB)
__device__ float g_W1f[(size_t)128*16*4096];     // [Wih1|Whh1] fragment-linear tf32 (32MB)
__device__ unsigned g_barGen, g_barCnt;

__device__ __forceinline__ uint32_t tf(float f){
    uint32_t r; asm("cvt.rna.tf32.f32 %0, %1;":"=r"(r):"f"(f)); return r;
}
__device__ __forceinline__ uint4 tf4(float4 v){
    uint4 o; o.x=tf(v.x); o.y=tf(v.y); o.z=tf(v.z); o.w=tf(v.w); return o;
}
__device__ __forceinline__ void mma8(float &d0,float &d1,float &d2,float &d3,
                                     uint4 a, uint32_t b0, uint32_t b1){
    asm volatile("mma.sync.aligned.m16n8k8.row.col.f32.tf32.tf32.f32 "
                 "{%0,%1,%2,%3},{%4,%5,%6,%7},{%8,%9},{%0,%1,%2,%3};"
                 :"+f"(d0),"+f"(d1),"+f"(d2),"+f"(d3)
                 :"r"(a.x),"r"(a.y),"r"(a.z),"r"(a.w),"r"(b0),"r"(b1));
}

__device__ __forceinline__ void gridbar(unsigned &gen){
    __syncthreads();
    if(threadIdx.x==0){
        const unsigned target=gen+1u;
        __threadfence();
        unsigned a=atomicAdd(&g_barCnt,1u);
        if(a==(unsigned)(gridDim.x-1)){ g_barCnt=0u; __threadfence(); atomicExch(&g_barGen,target); }
        else { while((int)(*((volatile unsigned*)&g_barGen)-target)<0){} }
        __threadfence();
    }
    gen++; __syncthreads();
}

// ---- one-time weight pre-gather into fragment-linear tf32 images ----------
__device__ void fill_weights(const float* Whh0,const float* Wih1,const float* Whh1){
    int gtid=blockIdx.x*NTHR+threadIdx.x;
    for(int idx=gtid; idx<1048576; idx+=NCTA*NTHR){     // W0f [r][c 8][ks 16][mt 2][lane 32]
        int lane=idx&31, wm=(idx>>5)&1, ks=(idx>>6)&15, c=(idx>>10)&7, r=idx>>13;
        int l0=wm*16+(lane>>2), l1=l0+8;
        int k=c*128+ks*8+(lane&3);
        int ga=(l0>>3)*HID + r*8 + (l0&7);
        int gb=(l1>>3)*HID + r*8 + (l1&7);
        uint4 v;
        v.x=tf(Whh0[(size_t)ga*HID+k]);
        v.y=tf(Whh0[(size_t)gb*HID+k]);
        v.z=tf(Whh0[(size_t)ga*HID+k+4]);
        v.w=tf(Whh0[(size_t)gb*HID+k+4]);
        ((uint4*)g_W0f)[idx]=v;
    }
    for(int idx=gtid; idx<2097152; idx+=NCTA*NTHR){     // W1f [r][c 16][ks 16][mt 2][lane 32]
        int lane=idx&31, wm=(idx>>5)&1, ks=(idx>>6)&15, c=(idx>>10)&15, r=idx>>14;
        int l0=wm*16+(lane>>2), l1=l0+8;
        int k=c*128+ks*8+(lane&3);
        int ga=(l0>>3)*HID + r*8 + (l0&7);
        int gb=(l1>>3)*HID + r*8 + (l1&7);
        const float* S=(k<HID)? Wih1 : Whh1;
        int kk=(k<HID)? k : k-HID;
        uint4 v;
        v.x=tf(S[(size_t)ga*HID+kk]);
        v.y=tf(S[(size_t)gb*HID+kk]);
        v.z=tf(S[(size_t)ga*HID+kk+4]);
        v.w=tf(S[(size_t)gb*HID+kk+4]);
        ((uint4*)g_W1f)[idx]=v;
    }
}
__device__ void prefill(const float* h0){
    int gtid=blockIdx.x*NTHR+threadIdx.x;
    for(int idx=gtid; idx<HID*BATCH; idx+=NCTA*NTHR){
        int k=idx>>6, b=idx&63;
        g_in1T[0][idx]=__uint_as_float(tf(h0[(size_t)b*HID+k]));
        g_in1T[1][(size_t)HID*BATCH+idx]=__uint_as_float(tf(h0[(size_t)BH+(size_t)b*HID+k]));
    }
}

// ---- phase A GEMM (R10-proven): XW0[s][n][b]=emb[x]@Wih0^T+b0 -------------
__device__ void phase_gemm(const int *xidx,const float *emb,int Kdim,
                           const float *W,const float *bias,float *C,float *sm){
    const int tid=threadIdx.x, lane=tid&31, wid=tid>>5;
    const int wm=wid&3, wn=wid>>2;
    uint32_t *AS=(uint32_t*)sm;          // [128][132]
    uint32_t *BS=(uint32_t*)(sm+16896);  // [64][132]
    const int g=lane>>2, tg=lane&3;
    for(int tile=blockIdx.x; tile<128*64; tile+=NCTA){
        const int mt=tile>>6, ntg=tile&63;
        const int m0=mt*128, n0=ntg*64;
        float d[2][4][4];
#pragma unroll
        for(int a=0;a<2;a++)
#pragma unroll
        for(int b=0;b<4;b++)
#pragma unroll
        for(int c=0;c<4;c++) d[a][b][c]=0.f;
        for(int kc=0; kc<Kdim/128; kc++){
            __syncthreads();
#pragma unroll
            for(int i=0;i<16;i++){
                int idx=tid+i*NTHR, rr=idx>>5, q=idx&31;
                const float *src=emb+(size_t)xidx[m0+rr]*EMBD + kc*128 + 4*q;
                *(uint4*)&AS[rr*132+4*q]=tf4(*(const float4*)src);
            }
#pragma unroll
            for(int i=0;i<8;i++){
                int idx=tid+i*NTHR, rr=idx>>5, q=idx&31;
                float4 v=*(const float4*)&W[(size_t)(n0+rr)*Kdim + kc*128 + 4*q];
                *(uint4*)&BS[rr*132+4*q]=tf4(v);
            }
            __syncthreads();
#pragma unroll 4
            for(int ks=0; ks<16; ks++){
                const int kk=ks*8+tg;
                uint4 af[2]; uint32_t b0[4],b1[4];
#pragma unroll
                for(int mi=0;mi<2;mi++){
                    int m=wm*32+mi*16+g;
                    af[mi].x=AS[m*132+kk];   af[mi].y=AS[(m+8)*132+kk];
                    af[mi].z=AS[m*132+kk+4]; af[mi].w=AS[(m+8)*132+kk+4];
                }
#pragma unroll
                for(int nt=0;nt<4;nt++){
                    int n=wn*32+nt*8+g;
                    b0[nt]=BS[n*132+kk]; b1[nt]=BS[n*132+kk+4];
                }
#pragma unroll
                for(int mi=0;mi<2;mi++)
#pragma unroll
                for(int nt=0;nt<4;nt++)
                    mma8(d[mi][nt][0],d[mi][nt][1],d[mi][nt][2],d[mi][nt][3],
                         af[mi],b0[nt],b1[nt]);
            }
        }
#pragma unroll
        for(int mi=0;mi<2;mi++){
            int m=m0+wm*32+mi*16+g;
            int s1=m>>6, bt1=m&63, s2=(m+8)>>6, bt2=(m+8)&63;
#pragma unroll
            for(int nt=0;nt<4;nt++){
                int n=n0+wn*32+nt*8+2*tg;
                size_t ba=((size_t)s1*GATE+n)*64+bt1;
                C[ba]   =d[mi][nt][0]+bias[n];
                C[ba+64]=d[mi][nt][1]+bias[n+1];
                size_t bb=((size_t)s2*GATE+n)*64+bt2;
                C[bb]   =d[mi][nt][2]+bias[n];
                C[bb+64]=d[mi][nt][3]+bias[n+1];
            }
        }
    }
}

// ---- one wavefront: CTA r does L0 step w (w<SEQ) + L1 step w-1 (w>=1) -----
// 8 warps = wn(2) x wk4(4); m-split is IN-WARP (mt loop) -> B LDS per MMA halved.
__device__ void wave_step(int w,float* cst0,float* cst1,
                          float* outH0,float* outC0,float* outH1,float* outC1,
                          float* sm){
    const int tid=threadIdx.x, lane=tid&31, wid=tid>>5;
    const int wn=wid>>2, wk4=wid&3;
    const int g=lane>>2, tg=lane&3;
    const int r=blockIdx.x;
    const bool doL0=(w<SEQ), doL1=(w>=1);
    const float* bufR=g_in1T[w&1];
    float* bufW=g_in1T[(w+1)&1];
    const uint4* A0g=(const uint4*)g_W0f + (size_t)r*8192;
    const uint4* A1g=(const uint4*)g_W1f + (size_t)r*16384;
    uint4* A0s=(uint4*)(sm+A0_F);
    uint4* A1s=(uint4*)(sm+A1_F);
    uint32_t* BSs=(uint32_t*)(sm+BS_F);
    float* GS=sm+GS_F;

    // prefetch this step's XW gates (independent of h)
    float xw[2][4];
    if(doL0){
#pragma unroll
        for(int i=0;i<2;i++){
            int p=tid+i*NTHR, u=p>>6, b=p&63;
            size_t base=((size_t)w*GATE + r*8+u)*64 + b;
#pragma unroll
            for(int gt=0;gt<4;gt++) xw[i][gt]=g_XW[base+(size_t)gt*(HID*64)];
        }
    }
    // stage chunk 0 (regs -> STS), R10 pattern
    uint4 rB[8], rA0[4], rA1[4];
#pragma unroll
    for(int i=0;i<8;i++) rB[i]=*(const uint4*)&bufR[(size_t)(tid+i*NTHR)*4];
    if(doL0){
#pragma unroll
        for(int i=0;i<4;i++) rA0[i]=A0g[tid+i*NTHR];
    }
    if(doL1){
#pragma unroll
        for(int i=0;i<4;i++) rA1[i]=A1g[tid+i*NTHR];
    }
#pragma unroll
    for(int i=0;i<8;i++){
        int idx=tid+i*NTHR, k=idx>>4, q=idx&15;
        *(uint4*)&BSs[k*72+4*q]=rB[i];
    }
    if(doL0){
#pragma unroll
        for(int i=0;i<4;i++) A0s[tid+i*NTHR]=rA0[i];
    }
    if(doL1){
#pragma unroll
        for(int i=0;i<4;i++) A1s[tid+i*NTHR]=rA1[i];
    }
    __syncthreads();

    float d0[2][4][4], d1[2][4][4];
#pragma unroll
    for(int m=0;m<2;m++)
#pragma unroll
    for(int a=0;a<4;a++)
#pragma unroll
    for(int b=0;b<4;b++){ d0[m][a][b]=0.f; d1[m][a][b]=0.f; }

    for(int c=0;c<16;c++){
        if(c<15){
#pragma unroll
            for(int i=0;i<8;i++)
                rB[i]=*(const uint4*)&bufR[((size_t)(c+1)*2048 + tid+i*NTHR)*4];
            if(doL0 && c+1<8){
#pragma unroll
                for(int i=0;i<4;i++) rA0[i]=A0g[(c+1)*1024 + tid+i*NTHR];
            }
            if(doL1){
#pragma unroll
                for(int i=0;i<4;i++) rA1[i]=A1g[(c+1)*1024 + tid+i*NTHR];
            }
        }
        const uint4* A0=A0s+(c&1)*1024;
        const uint4* A1=A1s+(c&1)*1024;
        const uint32_t* BS=BSs+(c&1)*9216;
#pragma unroll
        for(int ks2=0;ks2<4;ks2++){
            const int ksl=wk4*4+ks2, kcol=ksl*8+tg;
            uint32_t b0[4],b1[4];
#pragma unroll
            for(int nt=0;nt<4;nt++){
                int n=wn*32+nt*8+g;
                b0[nt]=BS[kcol*72+n]; b1[nt]=BS[(kcol+4)*72+n];
            }
            if(doL0 && c<8){
                uint4 a00=A0[(ksl*2+0)*32+lane];
                uint4 a01=A0[(ksl*2+1)*32+lane];
#pragma unroll
                for(int nt=0;nt<4;nt++){
                    mma8(d0[0][nt][0],d0[0][nt][1],d0[0][nt][2],d0[0][nt][3],a00,b0[nt],b1[nt]);
                    mma8(d0[1][nt][0],d0[1][nt][1],d0[1][nt][2],d0[1][nt][3],a01,b0[nt],b1[nt]);
                }
            }
            if(doL1){
                uint4 a10=A1[(ksl*2+0)*32+lane];
                uint4 a11=A1[(ksl*2+1)*32+lane];
#pragma unroll
                for(int nt=0;nt<4;nt++){
                    mma8(d1[0][nt][0],d1[0][nt][1],d1[0][nt][2],d1[0][nt][3],a10,b0[nt],b1[nt]);
                    mma8(d1[1][nt][0],d1[1][nt][1],d1[1][nt][2],d1[1][nt][3],a11,b0[nt],b1[nt]);
                }
            }
        }
        if(c<15){
#pragma unroll
            for(int i=0;i<8;i++){
                int idx=tid+i*NTHR, k=idx>>4, q=idx&15;
                *(uint4*)&BSs[((c+1)&1)*9216 + k*72+4*q]=rB[i];
            }
            if(doL0 && c+1<8){
#pragma unroll
                for(int i=0;i<4;i++) A0s[((c+1)&1)*1024 + tid+i*NTHR]=rA0[i];
            }
            if(doL1){
#pragma unroll
                for(int i=0;i<4;i++) A1s[((c+1)&1)*1024 + tid+i*NTHR]=rA1[i];
            }
        }
        __syncthreads();
    }
    // L0 epilogue (GS overlays B stage; all MMA reads done) + pointwise
    if(doL0){
#pragma unroll
        for(int mt=0;mt<2;mt++){
#pragma unroll
            for(int nt=0;nt<4;nt++){
                int m=mt*16+g, n=wn*32+nt*8+2*tg;
                GS[wk4*2304+m*72+n]      =d0[mt][nt][0];
                GS[wk4*2304+m*72+n+1]    =d0[mt][nt][1];
                GS[wk4*2304+(m+8)*72+n]  =d0[mt][nt][2];
                GS[wk4*2304+(m+8)*72+n+1]=d0[mt][nt][3];
            }
        }
    }
    __syncthreads();
    if(doL0){
#pragma unroll
        for(int i=0;i<2;i++){
            int p=tid+i*NTHR, u=p>>6, b=p&63;
            float ig=xw[i][0], fg=xw[i][1], gg=xw[i][2], og=xw[i][3];
#pragma unroll
            for(int q=0;q<4;q++){
                ig+=GS[q*2304+(0*8+u)*72+b];
                fg+=GS[q*2304+(1*8+u)*72+b];
                gg+=GS[q*2304+(2*8+u)*72+b];
                og+=GS[q*2304+(3*8+u)*72+b];
            }
            ig=1.f/(1.f+__expf(-ig)); fg=1.f/(1.f+__expf(-fg));
            og=1.f/(1.f+__expf(-og)); gg=tanhf(gg);
            float cc=fg*cst0[i]+ig*gg; cst0[i]=cc;
            float h=og*tanhf(cc);
            bufW[(r*8+u)*64+b]=__uint_as_float(tf(h));
            if(w==SEQ-1){ outH0[b*HID+r*8+u]=h; outC0[b*HID+r*8+u]=cc; }
        }
    }
    __syncthreads();
    // L1 epilogue + pointwise
    if(doL1){
#pragma unroll
        for(int mt=0;mt<2;mt++){
#pragma unroll
            for(int nt=0;nt<4;nt++){
                int m=mt*16+g, n=wn*32+nt*8+2*tg;
                GS[wk4*2304+m*72+n]      =d1[mt][nt][0];
                GS[wk4*2304+m*72+n+1]    =d1[mt][nt][1];
                GS[wk4*2304+(m+8)*72+n]  =d1[mt][nt][2];
                GS[wk4*2304+(m+8)*72+n+1]=d1[mt][nt][3];
            }
        }
    }
    __syncthreads();
    if(doL1){
#pragma unroll
        for(int i=0;i<2;i++){
            int p=tid+i*NTHR, u=p>>6, b=p&63;
            float ig=sm[BIAS_F+0*8+u], fg=sm[BIAS_F+1*8+u];
            float gg=sm[BIAS_F+2*8+u], og=sm[BIAS_F+3*8+u];
#pragma unroll
            for(int q=0;q<4;q++){
                ig+=GS[q*2304+(0*8+u)*72+b];
                fg+=GS[q*2304+(1*8+u)*72+b];
                gg+=GS[q*2304+(2*8+u)*72+b];
                og+=GS[q*2304+(3*8+u)*72+b];
            }
            ig=1.f/(1.f+__expf(-ig)); fg=1.f/(1.f+__expf(-fg));
            og=1.f/(1.f+__expf(-og)); gg=tanhf(gg);
            float cc=fg*cst1[i]+ig*gg; cst1[i]=cc;
            float h=og*tanhf(cc);
            bufW[(size_t)(1024+r*8+u)*64+b]=__uint_as_float(tf(h));
            if(w-1==SEQ-1){ outH1[b*HID+r*8+u]=h; outC1[b*HID+r*8+u]=cc; }
        }
    }
}

__global__ void __launch_bounds__(NTHR,1) lstm_all_kernel(
    const int *x,const float *h0,const float *c0,const float *embt,
    const float *Wih0,const float *Whh0,const float *b0,
    const float *Wih1,const float *Whh1,const float *b1,
    const float *Wfc,const float *bfc,float *out){
    extern __shared__ float sm[];
    unsigned gen=*((volatile unsigned*)&g_barGen);
    const int r=blockIdx.x, tid=threadIdx.x;

    fill_weights(Whh0,Wih1,Whh1);
    prefill(h0);
    phase_gemm(x,embt,EMBD,Wih0,b0,g_XW,sm);
    gridbar(gen);
    if(tid<32) sm[BIAS_F+tid]=b1[(tid>>3)*HID + r*8 + (tid&7)];  // after phase (smem reuse)
    __syncthreads();

    float cst0[2],cst1[2];
#pragma unroll
    for(int i=0;i<2;i++){
        int p=tid+i*NTHR, u=p>>6, b=p&63;
        cst0[i]=c0[(size_t)b*HID + r*8+u];
        cst1[i]=c0[(size_t)BH + (size_t)b*HID + r*8+u];
    }
    float* outH0=out+VOCAB*BATCH;
    float* outH1=out+VOCAB*BATCH+BH;
    float* outC0=out+VOCAB*BATCH+2*BH;
    float* outC1=out+VOCAB*BATCH+3*BH;

    for(int w=0;w<=SEQ;w++){
        wave_step(w,cst0,cst1,outH0,outC0,outH1,outC1,sm);
        gridbar(gen);
    }
    // FC: logits[b][v] = h1_last . Wfc[v] + bfc[v]  (one v per CTA)
    if(tid<BATCH){
        float s=0.f;
#pragma unroll 4
        for(int k=0;k<HID;k+=4){
            float4 hh=*(const float4*)&outH1[tid*HID+k];
            float4 ww=*(const float4*)&Wfc[(size_t)r*HID+k];
            s+=hh.x*ww.x+hh.y*ww.y+hh.z*ww.z+hh.w*ww.w;
        }
        out[tid*VOCAB+r]=s+bfc[r];
    }
}

extern "C" void kernel_launch(void *const *d_in,const int *in_sizes,int n_in,
                              void *d_out,int out_size){
    const int   *x   =(const int*)d_in[0];
    const float *h0  =(const float*)d_in[1];
    const float *c0  =(const float*)d_in[2];
    const float *embt=(const float*)d_in[3];
    const float *Wih0=(const float*)d_in[4];
    const float *Whh0=(const float*)d_in[5];
    const float *b0  =(const float*)d_in[6];
    const float *Wih1=(const float*)d_in[7];
    const float *Whh1=(const float*)d_in[8];
    const float *b1  =(const float*)d_in[9];
    const float *Wfc =(const float*)d_in[10];
    const float *bfc =(const float*)d_in[11];
    float *out=(float*)d_out;
    const int smemBytes=SMEM_FLOATS*(int)sizeof(float);   // 139,392 B
    cudaFuncSetAttribute(lstm_all_kernel,
                         cudaFuncAttributeMaxDynamicSharedMemorySize,smemBytes);
    lstm_all_kernel<<<NCTA,NTHR,smemBytes>>>(x,h0,c0,embt,Wih0,Whh0,b0,
                                             Wih1,Whh1,b1,Wfc,bfc,out);
}